// round 3
// baseline (speedup 1.0000x reference)
#include <cuda_runtime.h>

// out = -weight * sum_{k=0}^{M-1} f[k]*f[k+D] / (N-1),  M = (N-1)*D, D=2000.
//
// Single-wave persistent grid: 152 SMs x 4 blocks/SM = 608 blocks (GB300 has
// 152 SMs), each sweeping one contiguous segment. Contiguous sweep keeps the
// +8KB b-stream L1-resident for the a-stream (L2 traffic ~1x). Equal segments
// + exactly one wave -> no tail wave, no wave-transition overhead.
// Fused finalize via threadfence last-block-done (self-resetting counter).

#define NBLOCKS 608
#define NTHREADS 256

__device__ float g_partials[NBLOCKS];
__device__ unsigned int g_count = 0;

__global__ __launch_bounds__(NTHREADS)
void shifted_dot_fused(const float4* __restrict__ in4, long long Mv, int Dv,
                       const float* __restrict__ weight, float* __restrict__ out,
                       float inv_nm1) {
    const long long per = (Mv + gridDim.x - 1) / gridDim.x;
    const long long seg_beg = (long long)blockIdx.x * per;
    long long seg_end = seg_beg + per;
    if (seg_end > Mv) seg_end = Mv;

    float acc = 0.0f;
    long long t = seg_beg + threadIdx.x;

    // 4x unrolled: 8 outstanding 16B loads per thread per iteration.
    for (; t + 3 * NTHREADS < seg_end; t += 4 * NTHREADS) {
        float4 a0 = in4[t];
        float4 a1 = in4[t + NTHREADS];
        float4 a2 = in4[t + 2 * NTHREADS];
        float4 a3 = in4[t + 3 * NTHREADS];
        float4 b0 = in4[t + Dv];
        float4 b1 = in4[t + NTHREADS + Dv];
        float4 b2 = in4[t + 2 * NTHREADS + Dv];
        float4 b3 = in4[t + 3 * NTHREADS + Dv];
        acc += a0.x * b0.x + a0.y * b0.y + a0.z * b0.z + a0.w * b0.w;
        acc += a1.x * b1.x + a1.y * b1.y + a1.z * b1.z + a1.w * b1.w;
        acc += a2.x * b2.x + a2.y * b2.y + a2.z * b2.z + a2.w * b2.w;
        acc += a3.x * b3.x + a3.y * b3.y + a3.z * b3.z + a3.w * b3.w;
    }
    for (; t < seg_end; t += NTHREADS) {
        float4 a = in4[t];
        float4 b = in4[t + Dv];
        acc += a.x * b.x + a.y * b.y + a.z * b.z + a.w * b.w;
    }

    // block reduce
    #pragma unroll
    for (int o = 16; o > 0; o >>= 1)
        acc += __shfl_xor_sync(0xffffffff, acc, o);

    __shared__ float s[NTHREADS / 32];
    if ((threadIdx.x & 31) == 0) s[threadIdx.x >> 5] = acc;
    __syncthreads();

    __shared__ bool is_last;
    if (threadIdx.x == 0) {
        float v = 0.0f;
        #pragma unroll
        for (int i = 0; i < NTHREADS / 32; i++) v += s[i];
        g_partials[blockIdx.x] = v;
        __threadfence();
        unsigned int old = atomicAdd(&g_count, 1u);
        is_last = (old == gridDim.x - 1);
    }
    __syncthreads();

    if (is_last) {
        // final reduction over all block partials (fixed order -> deterministic)
        const volatile float* p = g_partials;
        float v = 0.0f;
        for (int i = threadIdx.x; i < (int)gridDim.x; i += NTHREADS)
            v += p[i];
        #pragma unroll
        for (int o = 16; o > 0; o >>= 1)
            v += __shfl_xor_sync(0xffffffff, v, o);

        __shared__ float s2[NTHREADS / 32];
        if ((threadIdx.x & 31) == 0) s2[threadIdx.x >> 5] = v;
        __syncthreads();
        if (threadIdx.x == 0) {
            float tot = 0.0f;
            #pragma unroll
            for (int i = 0; i < NTHREADS / 32; i++) tot += s2[i];
            out[0] = -(*weight) * tot * inv_nm1;
            g_count = 0;  // reset for next graph replay
        }
    }
}

extern "C" void kernel_launch(void* const* d_in, const int* in_sizes, int n_in,
                              void* d_out, int out_size) {
    const float* factor = (const float*)d_in[0];
    const float* weight = (const float*)d_in[1];
    float* out = (float*)d_out;

    const int D = 2000;
    const long long total = (long long)in_sizes[0];   // N * D
    const long long N = total / D;
    const long long M = (N - 1) * (long long)D;       // pair elements, divisible by 4
    const long long Mv = M / 4;                       // float4 count
    const int Dv = D / 4;

    shifted_dot_fused<<<NBLOCKS, NTHREADS>>>(
        (const float4*)factor, Mv, Dv, weight, out, 1.0f / (float)(N - 1));
}

// round 4
// speedup vs baseline: 1.0159x; 1.0159x over previous
#include <cuda_runtime.h>

// out = -weight * sum_{k=0}^{M-1} f[k]*f[k+D] / (N-1),  M = (N-1)*D, D=2000.
//
// Single FULL-residency wave: 152 SMs x 8 blocks/SM (regs=42 -> 8 x 256thr
// resident) = 1216 blocks, 64 warps/SM. Each block sweeps one contiguous
// segment so the +8KB b-stream load warms L1 for the a-stream (L2 ~1x).
// Exactly one wave -> no tail. Fused finalize via last-block-done counter.

#define NBLOCKS 1216
#define NTHREADS 256

__device__ float g_partials[NBLOCKS];
__device__ unsigned int g_count = 0;

__global__ __launch_bounds__(NTHREADS)
void shifted_dot_fused(const float4* __restrict__ in4, long long Mv, int Dv,
                       const float* __restrict__ weight, float* __restrict__ out,
                       float inv_nm1) {
    const long long per = (Mv + gridDim.x - 1) / gridDim.x;
    const long long seg_beg = (long long)blockIdx.x * per;
    long long seg_end = seg_beg + per;
    if (seg_end > Mv) seg_end = Mv;

    float acc = 0.0f;
    long long t = seg_beg + threadIdx.x;

    // 4x unrolled: 8 outstanding 16B loads per thread per iteration.
    for (; t + 3 * NTHREADS < seg_end; t += 4 * NTHREADS) {
        float4 a0 = in4[t];
        float4 a1 = in4[t + NTHREADS];
        float4 a2 = in4[t + 2 * NTHREADS];
        float4 a3 = in4[t + 3 * NTHREADS];
        float4 b0 = in4[t + Dv];
        float4 b1 = in4[t + NTHREADS + Dv];
        float4 b2 = in4[t + 2 * NTHREADS + Dv];
        float4 b3 = in4[t + 3 * NTHREADS + Dv];
        acc += a0.x * b0.x + a0.y * b0.y + a0.z * b0.z + a0.w * b0.w;
        acc += a1.x * b1.x + a1.y * b1.y + a1.z * b1.z + a1.w * b1.w;
        acc += a2.x * b2.x + a2.y * b2.y + a2.z * b2.z + a2.w * b2.w;
        acc += a3.x * b3.x + a3.y * b3.y + a3.z * b3.z + a3.w * b3.w;
    }
    for (; t < seg_end; t += NTHREADS) {
        float4 a = in4[t];
        float4 b = in4[t + Dv];
        acc += a.x * b.x + a.y * b.y + a.z * b.z + a.w * b.w;
    }

    // block reduce
    #pragma unroll
    for (int o = 16; o > 0; o >>= 1)
        acc += __shfl_xor_sync(0xffffffff, acc, o);

    __shared__ float s[NTHREADS / 32];
    if ((threadIdx.x & 31) == 0) s[threadIdx.x >> 5] = acc;
    __syncthreads();

    __shared__ bool is_last;
    if (threadIdx.x == 0) {
        float v = 0.0f;
        #pragma unroll
        for (int i = 0; i < NTHREADS / 32; i++) v += s[i];
        g_partials[blockIdx.x] = v;
        __threadfence();
        unsigned int old = atomicAdd(&g_count, 1u);
        is_last = (old == gridDim.x - 1);
    }
    __syncthreads();

    if (is_last) {
        // final reduction over all block partials (fixed order -> deterministic)
        const volatile float* p = g_partials;
        float v = 0.0f;
        for (int i = threadIdx.x; i < (int)gridDim.x; i += NTHREADS)
            v += p[i];
        #pragma unroll
        for (int o = 16; o > 0; o >>= 1)
            v += __shfl_xor_sync(0xffffffff, v, o);

        __shared__ float s2[NTHREADS / 32];
        if ((threadIdx.x & 31) == 0) s2[threadIdx.x >> 5] = v;
        __syncthreads();
        if (threadIdx.x == 0) {
            float tot = 0.0f;
            #pragma unroll
            for (int i = 0; i < NTHREADS / 32; i++) tot += s2[i];
            out[0] = -(*weight) * tot * inv_nm1;
            g_count = 0;  // reset for next graph replay
        }
    }
}

extern "C" void kernel_launch(void* const* d_in, const int* in_sizes, int n_in,
                              void* d_out, int out_size) {
    const float* factor = (const float*)d_in[0];
    const float* weight = (const float*)d_in[1];
    float* out = (float*)d_out;

    const int D = 2000;
    const long long total = (long long)in_sizes[0];   // N * D
    const long long N = total / D;
    const long long M = (N - 1) * (long long)D;       // pair elements, divisible by 4
    const long long Mv = M / 4;                       // float4 count
    const int Dv = D / 4;

    shifted_dot_fused<<<NBLOCKS, NTHREADS>>>(
        (const float4*)factor, Mv, Dv, weight, out, 1.0f / (float)(N - 1));
}

// round 5
// speedup vs baseline: 1.0880x; 1.0710x over previous
#include <cuda_runtime.h>

// out = -weight * sum_{k=0}^{M-1} f[k]*f[k+D] / (N-1),  M = (N-1)*D, D=2000.
//
// Persistent full-residency grid (1216 blocks = 152 SM x 8) with DYNAMIC
// 32KB-chunk work stealing to defeat the ~2x per-CTA completion spread seen
// with static segments (occ was stuck ~52%). Determinism: partials are keyed
// by CHUNK id (fixed intra-chunk order, fixed final reduce order), so the fp
// sum is identical every call regardless of which block grabs which chunk.
// Contiguous sweep per chunk keeps the +8KB b-stream L1-resident.

#define NBLOCKS 1216
#define NTHREADS 256
#define CHUNK 2048            // float4 per chunk = 32KB
#define MAXCHUNKS 16384

__device__ float g_chunk_sum[MAXCHUNKS];
__device__ unsigned int g_next = 0;
__device__ unsigned int g_done = 0;

__global__ __launch_bounds__(NTHREADS)
void shifted_dot_dyn(const float4* __restrict__ in4, long long Mv, int Dv,
                     int nchunks,
                     const float* __restrict__ weight, float* __restrict__ out,
                     float inv_nm1) {
    __shared__ unsigned int s_chunk;
    __shared__ float s[NTHREADS / 32];

    for (;;) {
        if (threadIdx.x == 0) s_chunk = atomicAdd(&g_next, 1u);
        __syncthreads();
        const unsigned int c = s_chunk;
        if (c >= (unsigned int)nchunks) break;

        const long long beg = (long long)c * CHUNK;
        long long end = beg + CHUNK;
        if (end > Mv) end = Mv;

        float acc = 0.0f;
        long long t = beg + threadIdx.x;
        // CHUNK/NTHREADS = 8 strided iters; unroll 4 -> 8 loads in flight.
        for (; t + 3 * NTHREADS < end; t += 4 * NTHREADS) {
            float4 a0 = in4[t];
            float4 a1 = in4[t + NTHREADS];
            float4 a2 = in4[t + 2 * NTHREADS];
            float4 a3 = in4[t + 3 * NTHREADS];
            float4 b0 = in4[t + Dv];
            float4 b1 = in4[t + NTHREADS + Dv];
            float4 b2 = in4[t + 2 * NTHREADS + Dv];
            float4 b3 = in4[t + 3 * NTHREADS + Dv];
            acc += a0.x * b0.x + a0.y * b0.y + a0.z * b0.z + a0.w * b0.w;
            acc += a1.x * b1.x + a1.y * b1.y + a1.z * b1.z + a1.w * b1.w;
            acc += a2.x * b2.x + a2.y * b2.y + a2.z * b2.z + a2.w * b2.w;
            acc += a3.x * b3.x + a3.y * b3.y + a3.z * b3.z + a3.w * b3.w;
        }
        for (; t < end; t += NTHREADS) {
            float4 a = in4[t];
            float4 b = in4[t + Dv];
            acc += a.x * b.x + a.y * b.y + a.z * b.z + a.w * b.w;
        }

        #pragma unroll
        for (int o = 16; o > 0; o >>= 1)
            acc += __shfl_xor_sync(0xffffffff, acc, o);
        if ((threadIdx.x & 31) == 0) s[threadIdx.x >> 5] = acc;
        __syncthreads();
        if (threadIdx.x == 0) {
            float v = 0.0f;
            #pragma unroll
            for (int i = 0; i < NTHREADS / 32; i++) v += s[i];
            g_chunk_sum[c] = v;
        }
        // next iteration's first __syncthreads orders s reuse
    }

    // last block to finish does the (fixed-order) final reduction
    __shared__ bool is_last;
    if (threadIdx.x == 0) {
        __threadfence();
        unsigned int old = atomicAdd(&g_done, 1u);
        is_last = (old == gridDim.x - 1);
    }
    __syncthreads();

    if (is_last) {
        const volatile float* p = g_chunk_sum;
        float v = 0.0f;
        for (int i = threadIdx.x; i < nchunks; i += NTHREADS)
            v += p[i];
        #pragma unroll
        for (int o = 16; o > 0; o >>= 1)
            v += __shfl_xor_sync(0xffffffff, v, o);
        __shared__ float s2[NTHREADS / 32];
        if ((threadIdx.x & 31) == 0) s2[threadIdx.x >> 5] = v;
        __syncthreads();
        if (threadIdx.x == 0) {
            float tot = 0.0f;
            #pragma unroll
            for (int i = 0; i < NTHREADS / 32; i++) tot += s2[i];
            out[0] = -(*weight) * tot * inv_nm1;
            g_next = 0;   // reset for next graph replay
            g_done = 0;
        }
    }
}

extern "C" void kernel_launch(void* const* d_in, const int* in_sizes, int n_in,
                              void* d_out, int out_size) {
    const float* factor = (const float*)d_in[0];
    const float* weight = (const float*)d_in[1];
    float* out = (float*)d_out;

    const int D = 2000;
    const long long total = (long long)in_sizes[0];   // N * D
    const long long N = total / D;
    const long long M = (N - 1) * (long long)D;       // divisible by 4
    const long long Mv = M / 4;                       // float4 count
    const int Dv = D / 4;
    const int nchunks = (int)((Mv + CHUNK - 1) / CHUNK);  // ~16000 <= MAXCHUNKS

    shifted_dot_dyn<<<NBLOCKS, NTHREADS>>>(
        (const float4*)factor, Mv, Dv, nchunks, weight, out,
        1.0f / (float)(N - 1));
}